// round 17
// baseline (speedup 1.0000x reference)
#include <cuda_runtime.h>
#include <math.h>

// Problem dims
#define BB_ 16
#define T_ 64
#define S_ 32
#define F_ 128
#define H_ 128
#define NH_ 4

// ---------------- scratch (no allocations allowed) ----------------
__device__ float g_hid[BB_*H_*S_];       // 65536  hid (t=T-1), computed once
__device__ float g_att4[BB_*NH_*H_*S_];  // attention outputs (pre head-mean)
__device__ float g_part[3*32*BB_*H_];    // gate split-K partials
__device__ float g_h2[BB_*H_];           // decoder h2
__device__ double g_partKL[BB_];         // per-batch KL partials

// ---- sync state: each counter on its OWN 128B L2 line (polls must not share
// a line with arrivals/releases — LTS serializes per-address/line ops) ----
struct __align__(128) PadCtr { unsigned int v; unsigned int pad[31]; };
__device__ PadCtr g_cntP;                // barrier arrival count
__device__ PadCtr g_genP;                // barrier generation (poll target)
__device__ PadCtr g_klcntP;              // KL partial arrivals
__device__ PadCtr g_bcntP[BB_];          // per-batch A0->AB mini-barriers

#define NB_ 128

// ---- fence-free acquire/release primitives (gpu scope) ----
__device__ __forceinline__ unsigned int ld_acq_(unsigned int* p){
  unsigned int v;
  asm volatile("ld.acquire.gpu.global.u32 %0, [%1];" : "=r"(v) : "l"(p) : "memory");
  return v;
}
__device__ __forceinline__ unsigned int atom_add_acqrel_(unsigned int* p, unsigned int v){
  unsigned int old;
  asm volatile("atom.acq_rel.gpu.global.add.u32 %0, [%1], %2;" : "=r"(old) : "l"(p), "r"(v) : "memory");
  return old;
}
__device__ __forceinline__ void st_rel_(unsigned int* p, unsigned int v){
  asm volatile("st.release.gpu.global.u32 [%0], %1;" :: "l"(p), "r"(v) : "memory");
}
__device__ __forceinline__ void st_rlx_(unsigned int* p, unsigned int v){
  asm volatile("st.relaxed.gpu.global.u32 [%0], %1;" :: "l"(p), "r"(v) : "memory");
}

// Grid barrier: release-arrive + acquire-poll with nanosleep backoff.
__device__ __forceinline__ void grid_barrier(int nb, bool wait){
  __syncthreads();
  if (threadIdx.x == 0) {
    unsigned int gen = ld_acq_(&g_genP.v);
    unsigned int old = atom_add_acqrel_(&g_cntP.v, 1u);
    if (old == (unsigned int)nb - 1u) {
      st_rlx_(&g_cntP.v, 0u);
      st_rel_(&g_genP.v, gen + 1u);
    } else if (wait) {
      while (ld_acq_(&g_genP.v) == gen) { __nanosleep(128); }
    }
  }
  __syncthreads();
}

__device__ __forceinline__ unsigned int rotl32_(unsigned int v, int d){ return (v << d) | (v >> (32 - d)); }

// Neumaier compensated accumulate (kept in the cheap, KL-sensitive tail).
__device__ __forceinline__ void kadd_(float& s, float& c, float p){
  float t = s + p;
  c += (fabsf(s) >= fabsf(p)) ? ((s - t) + p) : ((p - t) + s);
  s = t;
}

// Exact JAX threefry2x32 (20 rounds), key = (k0, k1)
__device__ __forceinline__ void threefry2x32_(unsigned int k0, unsigned int k1,
    unsigned int c0, unsigned int c1, unsigned int& o0, unsigned int& o1)
{
  unsigned int ks2 = k0 ^ k1 ^ 0x1BD11BDAu;
  unsigned int x0 = c0 + k0, x1 = c1 + k1;
  const int ra[4] = {13,15,26,6};
  const int rb[4] = {17,29,16,24};
  #pragma unroll
  for (int i=0;i<4;i++){ x0 += x1; x1 = rotl32_(x1, ra[i]); x1 ^= x0; }
  x0 += k1; x1 += ks2 + 1u;
  #pragma unroll
  for (int i=0;i<4;i++){ x0 += x1; x1 = rotl32_(x1, rb[i]); x1 ^= x0; }
  x0 += ks2; x1 += k0 + 2u;
  #pragma unroll
  for (int i=0;i<4;i++){ x0 += x1; x1 = rotl32_(x1, ra[i]); x1 ^= x0; }
  x0 += k0; x1 += k1 + 3u;
  #pragma unroll
  for (int i=0;i<4;i++){ x0 += x1; x1 = rotl32_(x1, rb[i]); x1 ^= x0; }
  x0 += k1; x1 += ks2 + 4u;
  #pragma unroll
  for (int i=0;i<4;i++){ x0 += x1; x1 = rotl32_(x1, ra[i]); x1 ^= x0; }
  x0 += ks2; x1 += k0 + 5u;
  o0 = x0; o1 = x1;
}

// ---------------- fused encoder pass, 128 co-resident blocks x 1024 threads ---------
__global__ void __launch_bounds__(1024) enc_kernel(
    const float* __restrict__ xsrc,
    const float* __restrict__ w_enc, const float* __restrict__ b_enc,
    const float* __restrict__ wq, const float* __restrict__ bq,
    const float* __restrict__ wk, const float* __restrict__ bk,
    const float* __restrict__ wv, const float* __restrict__ bv,
    const float* __restrict__ Wii, const float* __restrict__ Wig, const float* __restrict__ Wio,
    const float* __restrict__ w_fc, const float* __restrict__ b_fc,
    unsigned int keylo, float* __restrict__ z_out, float* __restrict__ kl_out,
    int do_dec,
    const float* __restrict__ w_d1, const float* __restrict__ b_d1,
    const float* __restrict__ w_d2, const float* __restrict__ b_d2)
{
  // pool (floats), phased:
  //  A0:    xs[0..4127], ps[8192..8703]
  //  AB-p1: hsm[0..4095], wksm[4096..5119], wqsm[5120..6143], wvsm[6144..7167]
  //  AB-p2: kT[0..4127], vsm[4128..8223], qsm[8224..10271]
  __shared__ __align__(16) float pool[10272];
  int blk = blockIdx.x, tid = threadIdx.x;
  int warp = tid >> 5, lane = tid & 31;

  // ================= stage A0: hid once per (b, ht of 16 rows), split-F ============
  {
    float* xs = pool;            // 4128
    float* ps = pool + 8192;     // 512 partials from the hi half
    int b = blk >> 3, ht = blk & 7;
    const float* xb = xsrc + (size_t)b*(T_*S_*F_) + (size_t)(T_-1)*(S_*F_);
    for (int i = tid; i < 4096; i += 1024)
      xs[(i>>7)*129 + (i&127)] = xb[i];
    __syncthreads();
    int s = tid & 31, hl = (tid >> 5) & 15, hi = tid >> 9;  // hi = f-half
    int h = ht*16 + hl;
    float pa = 0.f, pb = 0.f;
    #pragma unroll
    for (int fb2 = 0; fb2 < 2; fb2++) {
      float p = 0.f;
      #pragma unroll 8
      for (int f0 = 0; f0 < 32; f0++) {
        int f = (hi*2 + fb2)*32 + f0;
        p = fmaf(xs[s*129+f], w_enc[(size_t)f*H_ + h], p);
      }
      if (fb2 == 0) pa = p; else pb = p;
    }
    float halfsum = pa + pb;
    if (hi) ps[tid - 512] = halfsum;
    __syncthreads();
    if (!hi)
      g_hid[b*(H_*S_) + h*S_ + s] = (halfsum + ps[tid]) + b_enc[h];
    // arrive on this batch's mini-barrier (release)
    __syncthreads();
    if (tid == 0) atom_add_acqrel_(&g_bcntP[b].v, 1u);
  }

  // ================= stage AB: qkv + attention, one (b,n,half) unit per block ======
  {
    float* hsm  = pool;            // phase 1
    float* wksm = pool + 4096;
    float* wqsm = pool + 5120;
    float* wvsm = pool + 6144;
    float* kT   = pool;            // phase 2 (kT[s*129+g])
    float* vsm  = pool + 4128;
    float* qsm  = pool + 8224;
    int b = blk >> 3, n = (blk >> 1) & 3, half = blk & 1;

    // mini-barrier: wait for this batch's 8 A0 producers (acquire, backoff)
    if (tid == 0) { while (ld_acq_(&g_bcntP[b].v) < 8u) { __nanosleep(64); } }
    __syncthreads();

    for (int i = tid; i < 4096; i += 1024)
      hsm[i] = g_hid[b*(H_*S_) + i];      // identical linear layout [h*32+s]
    {
      int rw = tid >> 5, cl = tid & 31;
      wksm[tid] = wk[rw*(S_*NH_) + n*S_ + cl];
      wqsm[tid] = wq[rw*(S_*NH_) + n*S_ + cl];
      wvsm[tid] = wv[rw*(S_*NH_) + n*S_ + cl];
    }
    __syncthreads();

    const float scale = 0.08838834764831845f; // 1/sqrt(H)
    bool doq = (warp >= half*16) && (warp < half*16 + 16);
    float accK[4] = {0.f,0.f,0.f,0.f};
    float accV[4] = {0.f,0.f,0.f,0.f};
    float accQ[4] = {0.f,0.f,0.f,0.f};
    #pragma unroll 4
    for (int sp = 0; sp < 32; sp++) {
      float wkv = wksm[sp*32 + lane];
      float wqv = wqsm[sp*32 + lane];
      float wvv = wvsm[sp*32 + lane];
      #pragma unroll
      for (int rr = 0; rr < 4; rr++) {
        float hv = hsm[(warp*4+rr)*32 + sp];   // broadcast
        accK[rr] = fmaf(hv, wkv, accK[rr]);
        accV[rr] = fmaf(hv, wvv, accV[rr]);
        if (doq) accQ[rr] = fmaf(hv, wqv, accQ[rr]);
      }
    }
    __syncthreads();   // phase-1 smem dead
    #pragma unroll
    for (int rr = 0; rr < 4; rr++) {
      int h = warp*4 + rr;
      kT[lane*129 + h] = accK[rr] + bk[n*S_+lane];
      vsm[h*32 + lane] = accV[rr] + bv[n*S_+lane];
      if (doq)
        qsm[(h - half*64)*32 + lane] = (accQ[rr] + bq[n*S_+lane]) * scale;
    }
    __syncthreads();

    size_t base = ((size_t)(b*NH_ + n))*(H_*S_);
    float q_reg[2];
    #pragma unroll
    for (int r = 0; r < 2; r++) q_reg[r] = qsm[(warp*2 + r)*32 + lane];

    float lg[2][4];
    #pragma unroll
    for (int r = 0; r < 2; r++)
      #pragma unroll
      for (int j = 0; j < 4; j++) lg[r][j] = 0.f;
    #pragma unroll 8
    for (int s = 0; s < 32; s++) {
      float kv0 = kT[s*129 + lane];
      float kv1 = kT[s*129 + lane + 32];
      float kv2 = kT[s*129 + lane + 64];
      float kv3 = kT[s*129 + lane + 96];
      #pragma unroll
      for (int r = 0; r < 2; r++) {
        float qv = __shfl_sync(0xffffffffu, q_reg[r], s);
        lg[r][0] = fmaf(qv, kv0, lg[r][0]);
        lg[r][1] = fmaf(qv, kv1, lg[r][1]);
        lg[r][2] = fmaf(qv, kv2, lg[r][2]);
        lg[r][3] = fmaf(qv, kv3, lg[r][3]);
      }
    }
    #pragma unroll
    for (int r = 0; r < 2; r++) {
      float m = fmaxf(fmaxf(lg[r][0],lg[r][1]), fmaxf(lg[r][2],lg[r][3]));
      #pragma unroll
      for (int o = 16; o; o >>= 1) m = fmaxf(m, __shfl_xor_sync(0xffffffffu, m, o));
      float ssum = 0.f;
      #pragma unroll
      for (int j = 0; j < 4; j++){ lg[r][j] = expf(lg[r][j]-m); ssum += lg[r][j]; }
      #pragma unroll
      for (int o = 16; o; o >>= 1) ssum += __shfl_xor_sync(0xffffffffu, ssum, o);
      float inv = 1.f/ssum;
      #pragma unroll
      for (int j = 0; j < 4; j++) lg[r][j] *= inv;
    }
    float accP[2][4];
    #pragma unroll
    for (int r = 0; r < 2; r++)
      #pragma unroll
      for (int gb = 0; gb < 4; gb++) accP[r][gb] = 0.f;
    #pragma unroll
    for (int gb = 0; gb < 4; gb++) {
      #pragma unroll 8
      for (int g0 = 0; g0 < 32; g0++) {
        int g = gb*32 + g0;
        float vv = vsm[g*32 + lane];
        #pragma unroll
        for (int r = 0; r < 2; r++) {
          float pwv = __shfl_sync(0xffffffffu, lg[r][gb], g0);
          accP[r][gb] = fmaf(pwv, vv, accP[r][gb]);
        }
      }
    }
    #pragma unroll
    for (int r = 0; r < 2; r++) {
      float acc = (accP[r][0]+accP[r][1]) + (accP[r][2]+accP[r][3]);
      g_att4[base + (size_t)(half*64 + warp*2 + r)*S_ + lane] = acc;
    }
  }
  grid_barrier(NB_, true);
  // reset mini-barrier counters for next pass / next graph replay
  if (blk < 16 && tid == 0) st_rlx_(&g_bcntP[blk].v, 0u);

  // ================= stage C: gate GEMM (fused head-mean+ReLU) ====================
  if (blk < 96) {
    float* as = pool;   // 16*128
    int gate = blk / 32, chunk = blk & 31;
    const float* Wm = (gate == 0) ? Wii : (gate == 1) ? Wig : Wio;
    int j0 = chunk*128;
    for (int i = tid; i < 16*128; i += 1024) {
      int bb = i >> 7, j = i & 127;
      size_t bbase = (size_t)bb*4*(H_*S_);
      int hs = j0 + j;
      float v = (g_att4[bbase + hs] + g_att4[bbase + 4096 + hs])
              + (g_att4[bbase + 8192 + hs] + g_att4[bbase + 12288 + hs]);
      v *= 0.25f;
      as[i] = v > 0.f ? v : 0.f;
    }
    __syncthreads();
    int m = tid & 127, oct = tid >> 7;   // oct 0..7, 2 batch rows each
    float acc[2][4];
    #pragma unroll
    for (int bbi = 0; bbi < 2; bbi++)
      #pragma unroll
      for (int jb = 0; jb < 4; jb++) acc[bbi][jb] = 0.f;
    #pragma unroll
    for (int jb = 0; jb < 4; jb++)
      #pragma unroll 8
      for (int j0i = 0; j0i < 32; j0i++) {
        int j = jb*32 + j0i;
        float w = Wm[(size_t)(j0+j)*H_ + m];
        #pragma unroll
        for (int bbi = 0; bbi < 2; bbi++)
          acc[bbi][jb] = fmaf(as[(oct*2+bbi)*128 + j], w, acc[bbi][jb]);
      }
    size_t cbase = ((size_t)(gate*32 + chunk))*(BB_*H_);
    #pragma unroll
    for (int bbi = 0; bbi < 2; bbi++)
      g_part[cbase + (oct*2+bbi)*H_ + m] =
        (acc[bbi][0]+acc[bbi][1]) + (acc[bbi][2]+acc[bbi][3]);
  }

  // barrier 3: blocks >= 16 arrive and exit; 0..15 continue to stage D'
  if (blk >= 16) { grid_barrier(NB_, false); return; }
  grid_barrier(NB_, true);

  // ================= stage D': per-b tail — reduce+LSTM+fc+reparam+KL(+dec) =======
  {
    float* s_g  = pool;          // 384
    float* s_h  = pool + 512;    // 128
    float* s_fc = pool + 768;    // 256
    float* s_z  = pool + 1024;   // 128
    float* h1   = pool + 1280;   // 128
    double* rd  = (double*)(pool + 2048);  // 128 doubles
    int b = blk;
    if (tid < 384) {
      int gate = tid >> 7, m = tid & 127;
      int r = b*128 + m;
      float s = 0.f, c = 0.f;
      #pragma unroll
      for (int ch = 0; ch < 32; ch++)
        kadd_(s, c, g_part[(size_t)(gate*32 + ch)*(BB_*H_) + r]);
      s_g[gate*128 + m] = s + c;
    }
    __syncthreads();
    if (tid < 128) {
      double iv = 1.0/(1.0 + exp(-(double)s_g[tid]));
      double gv = tanh((double)s_g[128 + tid]);
      double ov = 1.0/(1.0 + exp(-(double)s_g[256 + tid]));
      s_h[tid] = (float)(ov * tanh(iv * gv));
    }
    __syncthreads();
    if (tid < 256) {
      int c = tid;
      float s = 0.f, cc = 0.f;
      #pragma unroll 8
      for (int mm = 0; mm < 128; mm++)
        kadd_(s, cc, s_h[mm] * w_fc[mm*256 + c]);
      s_fc[c] = (s + cc) + b_fc[c];
    }
    __syncthreads();
    if (tid < 128) {
      int k = tid, idx = b*128 + k;
      float mu = s_fc[k];
      float lv = s_fc[128 + k];
      unsigned int o0, o1;
      threefry2x32_(0u, keylo, 0u, (unsigned int)idx, o0, o1);
      unsigned int bits = o0 ^ o1;
      float f = __uint_as_float((bits >> 9) | 0x3f800000u) - 1.0f;   // [0,1)
      const float lo = -0.99999994f;                                 // nextafter(-1,0)
      float u = fmaxf(lo, fmaf(f, 2.0f, lo));
      float eps = 1.4142135623730951f * erfinvf(u);
      float zv = fmaf(eps, expf(0.5f*lv), mu);
      z_out[idx] = zv;
      s_z[k] = zv;
      double dmu = (double)mu, dlv = (double)lv;
      rd[k] = 1.0 + dlv - dmu*dmu - exp(dlv);
    }
    __syncthreads();
    for (int o = 64; o; o >>= 1) {
      if (tid < o) rd[tid] += rd[tid + o];
      __syncthreads();
    }
    if (tid == 0) g_partKL[b] = rd[0];
    __syncthreads();
    if (b != 0 && tid == 0)
      atom_add_acqrel_(&g_klcntP.v, 1u);   // release partial KL

    if (do_dec) {
      if (tid < 128) {
        int c = tid;
        float p[4] = {0.f,0.f,0.f,0.f};
        #pragma unroll
        for (int jb = 0; jb < 4; jb++)
          #pragma unroll 8
          for (int j0 = 0; j0 < 32; j0++) {
            int j = jb*32 + j0;
            p[jb] = fmaf(s_z[j], w_d1[j*128+c], p[jb]);
          }
        h1[c] = fmaxf(((p[0]+p[1]) + (p[2]+p[3])) + b_d1[c], 0.f);
      }
      __syncthreads();
      if (tid < 128) {
        int c = tid;
        float p[4] = {0.f,0.f,0.f,0.f};
        #pragma unroll
        for (int jb = 0; jb < 4; jb++)
          #pragma unroll 8
          for (int j0 = 0; j0 < 32; j0++) {
            int j = jb*32 + j0;
            p[jb] = fmaf(h1[j], w_d2[j*128+c], p[jb]);
          }
        g_h2[b*128 + c] = fmaxf(((p[0]+p[1]) + (p[2]+p[3])) + b_d2[c], 0.f);
      }
    }

    // block 0 finalizes KL after all 15 partners arrive (backoff poll)
    if (b == 0 && tid == 0) {
      while (ld_acq_(&g_klcntP.v) < 15u) { __nanosleep(64); }
      double ks = 0.0;
      #pragma unroll
      for (int b2 = 0; b2 < 16; b2++) ks += g_partKL[b2];
      kl_out[0] = (float)(-0.5 * ks * (1.0/2048.0));
      st_rlx_(&g_klcntP.v, 0u);
    }
  }
}

// ---------------- big decode GEMM h2[16,128] @ w_d3[128,262144] + b_d3 ----------------
__device__ __forceinline__ unsigned long long pk2_(float a, float b){
  return (unsigned long long)__float_as_uint(a) | ((unsigned long long)__float_as_uint(b) << 32);
}

__global__ void __launch_bounds__(256) big_kernel(
    const float* __restrict__ w_d3, const float* __restrict__ b_d3, float* __restrict__ out)
{
  __shared__ unsigned long long hp[8*128];   // (b-pair, j) packed h2 values
  int tid = threadIdx.x;
  for (int i = tid; i < 1024; i += 256) {
    int p = i >> 7, j = i & 127;
    hp[i] = pk2_(g_h2[(2*p)*128 + j], g_h2[(2*p+1)*128 + j]);
  }
  __syncthreads();
  size_t m2 = (size_t)blockIdx.x*256 + tid;    // float2 column index, < 131072
  const float2* w2 = (const float2*)w_d3;
  float2 bv2 = ((const float2*)b_d3)[m2];
  unsigned long long accx[8], accy[8];
  unsigned long long bx = pk2_(bv2.x, bv2.x), by = pk2_(bv2.y, bv2.y);
  #pragma unroll
  for (int p = 0; p < 8; p++){ accx[p] = bx; accy[p] = by; }
  #pragma unroll 4
  for (int j = 0; j < 128; j++) {
    float2 w = __ldg(&w2[(size_t)j*131072 + m2]);
    unsigned long long wx = pk2_(w.x, w.x), wy = pk2_(w.y, w.y);
    #pragma unroll
    for (int p = 0; p < 8; p++) {
      unsigned long long hpair = hp[p*128 + j];
      asm("fma.rn.f32x2 %0, %1, %2, %3;" : "=l"(accx[p]) : "l"(hpair), "l"(wx), "l"(accx[p]));
      asm("fma.rn.f32x2 %0, %1, %2, %3;" : "=l"(accy[p]) : "l"(hpair), "l"(wy), "l"(accy[p]));
    }
  }
  float2* o2 = (float2*)out;
  #pragma unroll
  for (int p = 0; p < 8; p++) {
    float2 v0, v1;
    v0.x = __uint_as_float((unsigned int)accx[p]);
    v0.y = __uint_as_float((unsigned int)accy[p]);
    v1.x = __uint_as_float((unsigned int)(accx[p] >> 32));
    v1.y = __uint_as_float((unsigned int)(accy[p] >> 32));
    o2[(size_t)(2*p)*131072 + m2]   = v0;
    o2[(size_t)(2*p+1)*131072 + m2] = v1;
  }
}

// ---------------- launcher (3 launches total) ----------------
extern "C" void kernel_launch(void* const* d_in, const int* in_sizes, int n_in,
                              void* d_out, int out_size)
{
  (void)in_sizes; (void)n_in; (void)out_size;
  const float* x     = (const float*)d_in[0];
  const float* w_enc = (const float*)d_in[1];
  const float* b_enc = (const float*)d_in[2];
  const float* wq    = (const float*)d_in[3];
  const float* bq    = (const float*)d_in[4];
  const float* wk    = (const float*)d_in[5];
  const float* bk    = (const float*)d_in[6];
  const float* wv    = (const float*)d_in[7];
  const float* bv    = (const float*)d_in[8];
  const float* W_ii  = (const float*)d_in[9];
  const float* W_ig  = (const float*)d_in[13];
  const float* W_io  = (const float*)d_in[15];
  const float* w_fc  = (const float*)d_in[17];
  const float* b_fc  = (const float*)d_in[18];
  const float* w_d1  = (const float*)d_in[19];
  const float* b_d1  = (const float*)d_in[20];
  const float* w_d2  = (const float*)d_in[21];
  const float* b_d2  = (const float*)d_in[22];
  const float* w_d3  = (const float*)d_in[23];
  const float* b_d3  = (const float*)d_in[24];

  float* outp = (float*)d_out;
  float* xhat = outp;                  // [16,64,32,128] = 4194304
  float* z1   = outp + 4194304;        // [16,128]
  float* z2   = z1 + 2048;             // [16,128]
  float* kl1  = z2 + 2048;             // scalar
  float* kl2  = kl1 + 1;               // scalar

  // -------- pass 1: encode(x, key=1) + decode MLP --------
  enc_kernel<<<NB_, 1024>>>(x, w_enc, b_enc, wq, bq, wk, bk, wv, bv,
                            W_ii, W_ig, W_io, w_fc, b_fc,
                            1u, z1, kl1, 1, w_d1, b_d1, w_d2, b_d2);
  // -------- big decode GEMM --------
  big_kernel<<<512, 256>>>(w_d3, b_d3, xhat);
  // -------- pass 2: encode(x_hat1, key=2) --------
  enc_kernel<<<NB_, 1024>>>(xhat, w_enc, b_enc, wq, bq, wk, bk, wv, bv,
                            W_ii, W_ig, W_io, w_fc, b_fc,
                            2u, z2, kl2, 0, w_d1, b_d1, w_d2, b_d2);
}